// round 1
// baseline (speedup 1.0000x reference)
#include <cuda_runtime.h>
#include <cuda_bf16.h>
#include <math.h>

#define Bz 16
#define Sz 512
#define Hz 512
#define Vz 10000
#define Gz 2048
#define NCTA 128

// ---- scratch (static device globals: no runtime allocation allowed) ----
__device__ float g_emb [Bz*Sz*Hz];     // embeddings / layer inputs
__device__ float g_xproj[Bz*Sz*Gz];    // x-projection for current layer
__device__ float g_hs0 [Bz*Sz*Hz];     // layer-0 hidden states
__device__ float g_hs1 [Bz*Sz*Hz];     // layer-1 hidden states
__device__ float g_hid [Bz*Sz*128];    // relu(w1) activations
__device__ float g_h   [2*Hz*Bz];      // double-buffered h, layout [u][b]
__device__ unsigned g_bar[2];          // grid-barrier counters (one per scan)

// ------------------------------------------------------------------
__global__ void reset_kernel() { g_bar[0] = 0u; g_bar[1] = 0u; }

// emb[bs][h] = w_emb[h][src[bs]] + b_emb[h]
__global__ void embed_kernel(const int* __restrict__ src,
                             const float* __restrict__ w_emb,
                             const float* __restrict__ b_emb)
{
    int idx = blockIdx.x * 256 + threadIdx.x;
    if (idx >= Bz*Sz*Hz) return;
    int h  = idx & (Hz-1);
    int bs = idx >> 9;
    int v  = src[bs];
    g_emb[idx] = w_emb[h*Vz + v] + b_emb[h];
}

// ------------------------------------------------------------------
// C[M,N] = A[M,K] @ B[N,K]^T + bias[n] (+bias2[n]), optional relu.
// M % 64 == 0, K % 16 == 0; N guarded. 64x64 tile, BK=16, 4x4 microtile.
__global__ void __launch_bounds__(256)
gemm_nt(const float* __restrict__ A, const float* __restrict__ B,
        const float* __restrict__ bias, const float* __restrict__ bias2,
        float* __restrict__ C, int M, int N, int K, int relu)
{
    __shared__ float As[16*68];
    __shared__ float Bs[16*68];

    const int n0 = blockIdx.x * 64;
    const int m0 = blockIdx.y * 64;
    const int tid = threadIdx.x;

    const int lr = tid >> 2;        // 0..63 : row within tile
    const int lk = (tid & 3) * 4;   // 0,4,8,12 : k offset

    const float* Ap = A + (size_t)(m0 + lr) * K + lk;
    const float* Bp = B + (size_t)(n0 + lr) * K + lk;
    const bool bvalid = (n0 + lr) < N;

    const int tx = tid & 15;        // n microtile
    const int ty = tid >> 4;        // m microtile

    float acc[4][4];
#pragma unroll
    for (int i = 0; i < 4; i++)
#pragma unroll
        for (int j = 0; j < 4; j++) acc[i][j] = 0.f;

    for (int kb = 0; kb < K; kb += 16) {
        float4 a4 = *(const float4*)(Ap + kb);
        float4 b4 = bvalid ? *(const float4*)(Bp + kb) : make_float4(0.f,0.f,0.f,0.f);
        __syncthreads();
        As[(lk+0)*68 + lr] = a4.x; As[(lk+1)*68 + lr] = a4.y;
        As[(lk+2)*68 + lr] = a4.z; As[(lk+3)*68 + lr] = a4.w;
        Bs[(lk+0)*68 + lr] = b4.x; Bs[(lk+1)*68 + lr] = b4.y;
        Bs[(lk+2)*68 + lr] = b4.z; Bs[(lk+3)*68 + lr] = b4.w;
        __syncthreads();
#pragma unroll
        for (int k = 0; k < 16; k++) {
            float4 av = *(const float4*)&As[k*68 + ty*4];
            float4 bv = *(const float4*)&Bs[k*68 + tx*4];
            float a[4] = {av.x, av.y, av.z, av.w};
            float b[4] = {bv.x, bv.y, bv.z, bv.w};
#pragma unroll
            for (int i = 0; i < 4; i++)
#pragma unroll
                for (int j = 0; j < 4; j++)
                    acc[i][j] += a[i] * b[j];
        }
    }

    const int n = n0 + tx*4;
    const int m = m0 + ty*4;
#pragma unroll
    for (int j = 0; j < 4; j++) {
        if (n + j < N) {
            float bb = bias[n + j] + (bias2 ? bias2[n + j] : 0.f);
#pragma unroll
            for (int i = 0; i < 4; i++) {
                float v = acc[i][j] + bb;
                if (relu) v = fmaxf(v, 0.f);
                C[(size_t)(m + i) * N + (n + j)] = v;
            }
        }
    }
}

// ------------------------------------------------------------------
// Persistent LSTM scan. 128 CTAs x 256 threads, each CTA owns 4 hidden
// units (16 gate rows). w_hh slice + cell state resident in SMEM for all
// 512 steps; one atomic grid barrier per step; h double-buffered in gmem.
__device__ __forceinline__ void grid_barrier(unsigned* ctr, unsigned target)
{
    __syncthreads();
    if (threadIdx.x == 0) {
        __threadfence();
        atomicAdd(ctr, 1u);
        while (*((volatile unsigned*)ctr) < target) { }
    }
    __syncthreads();
}

__global__ void __launch_bounds__(256)
lstm_scan(const float* __restrict__ xproj, const float* __restrict__ w_hh,
          float* __restrict__ hs, unsigned* __restrict__ ctr)
{
    extern __shared__ float sm[];
    float* w_s   = sm;                 // [512][16]  (k-major x local-gate)
    float* h_s   = sm + 8192;          // [512][16]  (k-major x batch)
    float* part  = sm + 16384;         // [256][17]  reduction partials
    float* xp_s  = part + 256*17;      // [16][16]   x-projection slice
    float* act_s = xp_s + 256;         // [16][16]   activated gates
    float* c_s   = act_s + 256;        // [4][16]    cell state

    const int tid = threadIdx.x;
    const int u0  = blockIdx.x * 4;    // first hidden unit of this CTA

    // Load w_hh slice: local gate lg = j*4 + i -> global gate j*512 + u0 + i
    for (int idx = tid; idx < 16*512; idx += 256) {
        int lg = idx >> 9;
        int k  = idx & 511;
        int gate = (lg >> 2) * Hz + u0 + (lg & 3);
        w_s[k*16 + lg] = w_hh[(size_t)gate * Hz + k];
    }
    if (tid < 64) {
        c_s[tid] = 0.f;
        int ul = tid >> 4, b = tid & 15;
        g_h[(u0 + ul)*16 + b] = 0.f;   // init h buffer 0
    }

    unsigned epoch = 1;
    grid_barrier(ctr, NCTA * epoch);

    const int ks   = tid >> 4;           // 0..15 K-split
    const int tile = tid & 15;
    const int gt4  = (tile >> 2) * 4;    // gate group base (0,4,8,12)
    const int bt4  = (tile & 3) * 4;     // batch group base

    for (int t = 0; t < Sz; t++) {
        // x-projection slice for this step (scattered 4B loads)
        {
            int lg = tid >> 4, b = tid & 15;
            int gate = (lg >> 2) * Hz + u0 + (lg & 3);
            xp_s[tid] = xproj[((size_t)((b << 9) | t)) * Gz + gate];
        }
        // load h_prev (written by other CTAs -> bypass L1)
        {
            const float4* hg = (const float4*)(g_h + (t & 1) * 8192);
            float4* hd = (float4*)h_s;
#pragma unroll
            for (int i = 0; i < 8; i++)
                hd[tid + 256*i] = __ldcg(hg + tid + 256*i);
        }
        __syncthreads();

        float acc[4][4];
#pragma unroll
        for (int i = 0; i < 4; i++)
#pragma unroll
            for (int j = 0; j < 4; j++) acc[i][j] = 0.f;

        const int kb = ks * 32;
#pragma unroll
        for (int kk = 0; kk < 32; kk++) {
            int k = kb + kk;
            float4 h4 = *(const float4*)(h_s + k*16 + bt4);
            float4 w4 = *(const float4*)(w_s + k*16 + gt4);
            float hv[4] = {h4.x, h4.y, h4.z, h4.w};
            float wv[4] = {w4.x, w4.y, w4.z, w4.w};
#pragma unroll
            for (int gi = 0; gi < 4; gi++)
#pragma unroll
                for (int bi = 0; bi < 4; bi++)
                    acc[gi][bi] += wv[gi] * hv[bi];
        }
#pragma unroll
        for (int gi = 0; gi < 4; gi++)
#pragma unroll
            for (int bi = 0; bi < 4; bi++)
                part[((gt4+gi)*16 + (bt4+bi))*17 + ks] = acc[gi][bi];
        __syncthreads();

        // reduce K-splits + activation; tid -> (lg = tid/16, b = tid%16)
        {
            float s = xp_s[tid];
#pragma unroll
            for (int q = 0; q < 16; q++) s += part[tid*17 + q];
            int j = tid >> 6;  // gate type: 0=i 1=f 2=g 3=o
            float a = (j == 2) ? tanhf(s) : 1.f / (1.f + expf(-s));
            act_s[tid] = a;
        }
        __syncthreads();

        if (tid < 64) {
            int ul = tid >> 4, b = tid & 15;
            float iv = act_s[tid];
            float fv = act_s[tid + 64];
            float gv = act_s[tid + 128];
            float ov = act_s[tid + 192];
            float c = fv * c_s[tid] + iv * gv;
            c_s[tid] = c;
            float h = ov * tanhf(c);
            g_h[((t+1) & 1) * 8192 + (u0 + ul)*16 + b] = h;
            hs[((size_t)((b << 9) | t)) * Hz + u0 + ul] = h;
        }
        epoch++;
        grid_barrier(ctr, NCTA * epoch);
    }
}

// ------------------------------------------------------------------
extern "C" void kernel_launch(void* const* d_in, const int* in_sizes, int n_in,
                              void* d_out, int out_size)
{
    const int*   src   = (const int*)  d_in[0];
    const float* w_emb = (const float*)d_in[1];
    const float* b_emb = (const float*)d_in[2];
    const float* w_ih0 = (const float*)d_in[3];
    const float* w_hh0 = (const float*)d_in[4];
    const float* b_ih0 = (const float*)d_in[5];
    const float* b_hh0 = (const float*)d_in[6];
    const float* w_ih1 = (const float*)d_in[7];
    const float* w_hh1 = (const float*)d_in[8];
    const float* b_ih1 = (const float*)d_in[9];
    const float* b_hh1 = (const float*)d_in[10];
    const float* w1    = (const float*)d_in[11];
    const float* b1    = (const float*)d_in[12];
    const float* w2    = (const float*)d_in[13];
    const float* b2    = (const float*)d_in[14];
    float* out = (float*)d_out;

    float *emb, *xp, *hs0, *hs1, *hid;
    unsigned* bar;
    cudaGetSymbolAddress((void**)&emb, g_emb);
    cudaGetSymbolAddress((void**)&xp,  g_xproj);
    cudaGetSymbolAddress((void**)&hs0, g_hs0);
    cudaGetSymbolAddress((void**)&hs1, g_hs1);
    cudaGetSymbolAddress((void**)&hid, g_hid);
    cudaGetSymbolAddress((void**)&bar, g_bar);

    const int scan_smem = (8192 + 8192 + 256*17 + 256 + 256 + 64) * 4;
    cudaFuncSetAttribute(lstm_scan, cudaFuncAttributeMaxDynamicSharedMemorySize,
                         scan_smem);

    const int M = Bz * Sz;  // 8192

    // 1. embedding
    embed_kernel<<<(M*Hz + 255)/256, 256>>>(src, w_emb, b_emb);

    // reset barrier counters (stream-ordered before both scans)
    reset_kernel<<<1, 1>>>();

    // 2. layer-0 x-projection: [8192,512] @ [2048,512]^T
    gemm_nt<<<dim3(Gz/64, M/64), 256>>>(emb, w_ih0, b_ih0, b_hh0, xp,
                                        M, Gz, Hz, 0);
    // 3. layer-0 scan
    lstm_scan<<<NCTA, 256, scan_smem>>>(xp, w_hh0, hs0, bar);

    // 4. layer-1 x-projection
    gemm_nt<<<dim3(Gz/64, M/64), 256>>>(hs0, w_ih1, b_ih1, b_hh1, xp,
                                        M, Gz, Hz, 0);
    // 5. layer-1 scan
    lstm_scan<<<NCTA, 256, scan_smem>>>(xp, w_hh1, hs1, bar + 1);

    // 6. hid = relu(hs1 @ w1^T + b1): [8192,512] @ [128,512]^T
    gemm_nt<<<dim3(2, M/64), 256>>>(hs1, w1, b1, nullptr, hid,
                                    M, 128, Hz, 1);

    // 7. logits = hid @ w2^T + b2: [8192,128] @ [10000,128]^T
    gemm_nt<<<dim3((Vz + 63)/64, M/64), 256>>>(hid, w2, b2, nullptr, out,
                                               M, Vz, 128, 0);
}